// round 13
// baseline (speedup 1.0000x reference)
#include <cuda_runtime.h>
#include <cuda_fp16.h>
#include <mma.h>
#include <cstdint>

using namespace nvcuda;

#define N_NODES 50000
#define E_EDGES 800000
#define F 128
#define CAP 64             // max edges/dst (deg~Poisson(16); P(deg>64) ~ 1e-20)

// __device__ scratch (allocation-free rule)
__device__ __align__(16) __half g_hidden[(size_t)N_NODES * F];  // 12.8 MB
__device__ __align__(16) int  g_cnt[N_NODES + 12];              // padded for int4 zeroing
__device__ __align__(16) int2 g_slot[(size_t)N_NODES * CAP];    // 25.6 MB

#define BM 64
#define GEMM_BLOCKS ((N_NODES + BM - 1) / BM)              // 782
#define FILL_BLOCKS ((E_EDGES + 255) / 256)                // 3125
#define TOTAL_BLOCKS (GEMM_BLOCKS + FILL_BLOCKS)           // 3907

// ---------------------------------------------------------------------------
// Kernel A: zero per-dst counters (int4 stores)
// ---------------------------------------------------------------------------
__global__ void zero_cnt_kernel(int* __restrict__ cnt) {
    int i = blockIdx.x * blockDim.x + threadIdx.x;
    if (i < (N_NODES + 3) / 4)
        ((int4*)cnt)[i] = make_int4(0, 0, 0, 0);
}

// ---------------------------------------------------------------------------
// GEMM body — EXACT R8 structure (proven ~36us fused).  64x128 tile, full
// K=128 in smem (48KB).  8 warps (2x4), each 32x32 via 2x2 wmma frags.
// DO NOT restructure to 32KB/two-half form: costs +16us (R9/R10 measured).
// ---------------------------------------------------------------------------
__device__ __forceinline__ void gemm_body(
    const float* __restrict__ x,
    const float* __restrict__ W,
    const float* __restrict__ b,
    __half* __restrict__ hidden,
    unsigned char* smem_raw,
    int gemm_id)
{
    __half* xs  = (__half*)smem_raw;            // [64][128]
    __half* wsm = xs + 64 * 128;                // [128][128]
    float*  out_s = (float*)smem_raw;           // [64][128] (epilogue reuse)

    const int tid = threadIdx.x;
    const int block_row = gemm_id * BM;

    // ---- x tile fp32->fp16: 64x128 = 2048 float4, 8/thread ----
#pragma unroll
    for (int i = 0; i < 8; i++) {
        const int idx = tid + i * 256;
        const int r = idx >> 5;
        const int c4 = idx & 31;
        const int grow = block_row + r;
        float4 v = make_float4(0.f, 0.f, 0.f, 0.f);
        if (grow < N_NODES)
            v = *(const float4*)&x[(size_t)grow * F + c4 * 4];
        *(__half2*)&xs[r * 128 + c4 * 4]     = __floats2half2_rn(v.x, v.y);
        *(__half2*)&xs[r * 128 + c4 * 4 + 2] = __floats2half2_rn(v.z, v.w);
    }
    // ---- W fp32->fp16: 128x128 = 4096 float4, 16/thread ----
#pragma unroll
    for (int i = 0; i < 16; i++) {
        const int idx = tid + i * 256;
        const int n = idx >> 5;
        const int c4 = idx & 31;
        float4 v = *(const float4*)&W[(size_t)n * F + c4 * 4];
        *(__half2*)&wsm[n * 128 + c4 * 4]     = __floats2half2_rn(v.x, v.y);
        *(__half2*)&wsm[n * 128 + c4 * 4 + 2] = __floats2half2_rn(v.z, v.w);
    }
    __syncthreads();

    const int wid = tid >> 5;
    const int warp_m = wid & 1;
    const int warp_n = wid >> 1;

    wmma::fragment<wmma::accumulator, 16, 16, 16, float> acc[2][2];
#pragma unroll
    for (int im = 0; im < 2; im++)
#pragma unroll
        for (int jn = 0; jn < 2; jn++)
            wmma::fill_fragment(acc[im][jn], 0.f);

#pragma unroll
    for (int k0 = 0; k0 < F; k0 += 16) {
        wmma::fragment<wmma::matrix_a, 16, 16, 16, __half, wmma::row_major> a[2];
        wmma::fragment<wmma::matrix_b, 16, 16, 16, __half, wmma::col_major> bf[2];
#pragma unroll
        for (int im = 0; im < 2; im++)
            wmma::load_matrix_sync(a[im], &xs[(warp_m * 32 + im * 16) * 128 + k0], 128);
#pragma unroll
        for (int jn = 0; jn < 2; jn++)
            wmma::load_matrix_sync(bf[jn], &wsm[(warp_n * 32 + jn * 16) * 128 + k0], 128);
#pragma unroll
        for (int im = 0; im < 2; im++)
#pragma unroll
            for (int jn = 0; jn < 2; jn++)
                wmma::mma_sync(acc[im][jn], a[im], bf[jn], acc[im][jn]);
    }

    __syncthreads();
#pragma unroll
    for (int im = 0; im < 2; im++)
#pragma unroll
        for (int jn = 0; jn < 2; jn++)
            wmma::store_matrix_sync(
                &out_s[(warp_m * 32 + im * 16) * 128 + warp_n * 32 + jn * 16],
                acc[im][jn], 128, wmma::mem_row_major);
    __syncthreads();

#pragma unroll
    for (int i = 0; i < 8; i++) {
        const int idx = tid + i * 256;
        const int r = idx >> 5;
        const int c4 = idx & 31;
        const int grow = block_row + r;
        if (grow < N_NODES) {
            float4 v = *(const float4*)&out_s[r * 128 + c4 * 4];
            const float4 bias = *(const float4*)&b[c4 * 4];
            union { uint2 u; __half2 h[2]; } pk;
            pk.h[0] = __floats2half2_rn(v.x + bias.x, v.y + bias.y);
            pk.h[1] = __floats2half2_rn(v.z + bias.z, v.w + bias.w);
            *(uint2*)&hidden[(size_t)grow * F + c4 * 4] = pk.u;
        }
    }
}

// ---------------------------------------------------------------------------
// Fill body: bucket edges by dst.  edge_index int32 [2,E]: row0=dst, row1=src.
// ---------------------------------------------------------------------------
__device__ __forceinline__ void fill_body(
    const int* __restrict__ edge_index,
    const float* __restrict__ edge_weight,
    int* __restrict__ cnt,
    int2* __restrict__ slot,
    int fill_id)
{
    const int e = fill_id * 256 + threadIdx.x;
    if (e >= E_EDGES) return;
    const int dst = edge_index[e];
    const int src = edge_index[E_EDGES + e];
    const float w = edge_weight[e];
    const int pos = atomicAdd(&cnt[dst], 1);
    if (pos < CAP)
        slot[(size_t)dst * CAP + pos] = make_int2(src, __float_as_int(w));
}

// ---------------------------------------------------------------------------
// Fused kernel: range split, 48KB static smem (EXACT R8 config, proven).
// ---------------------------------------------------------------------------
__global__ __launch_bounds__(256) void gemm_fill_fused_kernel(
    const float* __restrict__ x,
    const float* __restrict__ W,
    const float* __restrict__ b,
    const int* __restrict__ edge_index,
    const float* __restrict__ edge_weight,
    __half* __restrict__ hidden,
    int* __restrict__ cnt,
    int2* __restrict__ slot)
{
    __shared__ __align__(16) unsigned char smem_raw[48 * 1024];
    const int bid = blockIdx.x;
    if (bid < GEMM_BLOCKS) {
        gemm_body(x, W, b, hidden, smem_raw, bid);
    } else {
        fill_body(edge_index, edge_weight, cnt, slot, bid - GEMM_BLOCKS);
    }
}

// ---------------------------------------------------------------------------
// Gather SpMM: one warp per dst node; lane l owns feats 4l..4l+3 (8 fp16 B).
// fp32 accumulation.  Unroll x8 with PLAIN int2 slot loads (deepens MLP to 8;
// single change vs R11's proven x4).  No int4 cast, no cnt reset.
// ---------------------------------------------------------------------------
#define GATHER_STEP(E)                                                        \
    do {                                                                      \
        const uint2 _r = *(const uint2*)&hidden[(size_t)(E).x * F + lane*4];  \
        const float _w = __int_as_float((E).y);                              \
        float2 _a01 = __half22float2(*(const __half2*)&_r.x);                \
        float2 _a23 = __half22float2(*(const __half2*)&_r.y);                \
        acc.x += _w * _a01.x; acc.y += _w * _a01.y;                          \
        acc.z += _w * _a23.x; acc.w += _w * _a23.y;                          \
    } while (0)

__global__ __launch_bounds__(256) void spmm_gather_kernel(
    const int* __restrict__ cnt_arr,
    const int2* __restrict__ slot,
    const __half* __restrict__ hidden,
    float* __restrict__ out)
{
    const int node = blockIdx.x * (blockDim.x >> 5) + (threadIdx.x >> 5);
    const int lane = threadIdx.x & 31;
    if (node >= N_NODES) return;

    int cnt = cnt_arr[node];
    if (cnt > CAP) cnt = CAP;
    const int2* __restrict__ sl = &slot[(size_t)node * CAP];

    float4 acc = make_float4(0.f, 0.f, 0.f, 0.f);

    int j = 0;
    for (; j + 8 <= cnt; j += 8) {
        const int2 e0 = sl[j];
        const int2 e1 = sl[j + 1];
        const int2 e2 = sl[j + 2];
        const int2 e3 = sl[j + 3];
        const int2 e4 = sl[j + 4];
        const int2 e5 = sl[j + 5];
        const int2 e6 = sl[j + 6];
        const int2 e7 = sl[j + 7];
        const uint2 r0 = *(const uint2*)&hidden[(size_t)e0.x * F + lane * 4];
        const uint2 r1 = *(const uint2*)&hidden[(size_t)e1.x * F + lane * 4];
        const uint2 r2 = *(const uint2*)&hidden[(size_t)e2.x * F + lane * 4];
        const uint2 r3 = *(const uint2*)&hidden[(size_t)e3.x * F + lane * 4];
        const uint2 r4 = *(const uint2*)&hidden[(size_t)e4.x * F + lane * 4];
        const uint2 r5 = *(const uint2*)&hidden[(size_t)e5.x * F + lane * 4];
        const uint2 r6 = *(const uint2*)&hidden[(size_t)e6.x * F + lane * 4];
        const uint2 r7 = *(const uint2*)&hidden[(size_t)e7.x * F + lane * 4];
        const float w0 = __int_as_float(e0.y);
        const float w1 = __int_as_float(e1.y);
        const float w2 = __int_as_float(e2.y);
        const float w3 = __int_as_float(e3.y);
        const float w4 = __int_as_float(e4.y);
        const float w5 = __int_as_float(e5.y);
        const float w6 = __int_as_float(e6.y);
        const float w7 = __int_as_float(e7.y);
        float2 a01, a23;
        a01 = __half22float2(*(const __half2*)&r0.x);
        a23 = __half22float2(*(const __half2*)&r0.y);
        acc.x += w0 * a01.x; acc.y += w0 * a01.y; acc.z += w0 * a23.x; acc.w += w0 * a23.y;
        a01 = __half22float2(*(const __half2*)&r1.x);
        a23 = __half22float2(*(const __half2*)&r1.y);
        acc.x += w1 * a01.x; acc.y += w1 * a01.y; acc.z += w1 * a23.x; acc.w += w1 * a23.y;
        a01 = __half22float2(*(const __half2*)&r2.x);
        a23 = __half22float2(*(const __half2*)&r2.y);
        acc.x += w2 * a01.x; acc.y += w2 * a01.y; acc.z += w2 * a23.x; acc.w += w2 * a23.y;
        a01 = __half22float2(*(const __half2*)&r3.x);
        a23 = __half22float2(*(const __half2*)&r3.y);
        acc.x += w3 * a01.x; acc.y += w3 * a01.y; acc.z += w3 * a23.x; acc.w += w3 * a23.y;
        a01 = __half22float2(*(const __half2*)&r4.x);
        a23 = __half22float2(*(const __half2*)&r4.y);
        acc.x += w4 * a01.x; acc.y += w4 * a01.y; acc.z += w4 * a23.x; acc.w += w4 * a23.y;
        a01 = __half22float2(*(const __half2*)&r5.x);
        a23 = __half22float2(*(const __half2*)&r5.y);
        acc.x += w5 * a01.x; acc.y += w5 * a01.y; acc.z += w5 * a23.x; acc.w += w5 * a23.y;
        a01 = __half22float2(*(const __half2*)&r6.x);
        a23 = __half22float2(*(const __half2*)&r6.y);
        acc.x += w6 * a01.x; acc.y += w6 * a01.y; acc.z += w6 * a23.x; acc.w += w6 * a23.y;
        a01 = __half22float2(*(const __half2*)&r7.x);
        a23 = __half22float2(*(const __half2*)&r7.y);
        acc.x += w7 * a01.x; acc.y += w7 * a01.y; acc.z += w7 * a23.x; acc.w += w7 * a23.y;
    }
    for (; j + 4 <= cnt; j += 4) {
        const int2 e0 = sl[j];
        const int2 e1 = sl[j + 1];
        const int2 e2 = sl[j + 2];
        const int2 e3 = sl[j + 3];
        const uint2 r0 = *(const uint2*)&hidden[(size_t)e0.x * F + lane * 4];
        const uint2 r1 = *(const uint2*)&hidden[(size_t)e1.x * F + lane * 4];
        const uint2 r2 = *(const uint2*)&hidden[(size_t)e2.x * F + lane * 4];
        const uint2 r3 = *(const uint2*)&hidden[(size_t)e3.x * F + lane * 4];
        const float w0 = __int_as_float(e0.y);
        const float w1 = __int_as_float(e1.y);
        const float w2 = __int_as_float(e2.y);
        const float w3 = __int_as_float(e3.y);
        float2 a01, a23;
        a01 = __half22float2(*(const __half2*)&r0.x);
        a23 = __half22float2(*(const __half2*)&r0.y);
        acc.x += w0 * a01.x; acc.y += w0 * a01.y; acc.z += w0 * a23.x; acc.w += w0 * a23.y;
        a01 = __half22float2(*(const __half2*)&r1.x);
        a23 = __half22float2(*(const __half2*)&r1.y);
        acc.x += w1 * a01.x; acc.y += w1 * a01.y; acc.z += w1 * a23.x; acc.w += w1 * a23.y;
        a01 = __half22float2(*(const __half2*)&r2.x);
        a23 = __half22float2(*(const __half2*)&r2.y);
        acc.x += w2 * a01.x; acc.y += w2 * a01.y; acc.z += w2 * a23.x; acc.w += w2 * a23.y;
        a01 = __half22float2(*(const __half2*)&r3.x);
        a23 = __half22float2(*(const __half2*)&r3.y);
        acc.x += w3 * a01.x; acc.y += w3 * a01.y; acc.z += w3 * a23.x; acc.w += w3 * a23.y;
    }
    for (; j < cnt; j++) {
        const int2 e0 = sl[j];
        GATHER_STEP(e0);
    }
    *(float4*)&out[(size_t)node * F + lane * 4] = acc;
}

// ---------------------------------------------------------------------------
// Launch
// Inputs: x [N,128] f32, edge_index [2,E] i32, edge_weight [E] f32,
//         W [128,128] f32, b [128] f32.  Output: [N,128] f32.
// ---------------------------------------------------------------------------
extern "C" void kernel_launch(void* const* d_in, const int* in_sizes, int n_in,
                              void* d_out, int out_size) {
    const float* x  = (const float*)d_in[0];
    const int*   ei = (const int*)d_in[1];
    const float* ew = (const float*)d_in[2];
    const float* W  = (const float*)d_in[3];
    const float* b  = (const float*)d_in[4];
    float* out = (float*)d_out;

    __half* hidden; int* cnt; int2* slot;
    cudaGetSymbolAddress((void**)&hidden, g_hidden);
    cudaGetSymbolAddress((void**)&cnt, g_cnt);
    cudaGetSymbolAddress((void**)&slot, g_slot);

    // A) zero per-dst counters
    {
        const int n4 = (N_NODES + 3) / 4;
        zero_cnt_kernel<<<(n4 + 255) / 256, 256>>>(cnt);
    }
    // B) HMMA GEMM (fp16 hidden, 48KB smem) overlapped with edge bucketing
    gemm_fill_fused_kernel<<<TOTAL_BLOCKS, 256>>>(x, W, b, ei, ew, hidden, cnt, slot);

    // C) out[dst] = sum w * hidden[src]  (gather; writes all rows)
    {
        const int warps_per_block = 256 / 32;
        const int grid = (N_NODES + warps_per_block - 1) / warps_per_block;
        spmm_gather_kernel<<<grid, 256>>>(cnt, slot, hidden, out);
    }
}

// round 14
// speedup vs baseline: 1.0014x; 1.0014x over previous
#include <cuda_runtime.h>
#include <cuda_fp16.h>
#include <mma.h>
#include <cstdint>

using namespace nvcuda;

#define N_NODES 50000
#define E_EDGES 800000
#define F 128
#define CAP 64             // max edges/dst (deg~Poisson(16); P(deg>64) ~ 1e-20)

// __device__ scratch (allocation-free rule)
__device__ __align__(16) __half g_hidden[(size_t)N_NODES * F];  // 12.8 MB
__device__ __align__(16) __half g_Wh[F * F];                    // 32 KB fp16 W
__device__ __align__(16) int  g_cnt[N_NODES + 12];              // padded for int4 zeroing
__device__ __align__(16) int2 g_slot[(size_t)N_NODES * CAP];    // 25.6 MB

#define BM 64
#define GEMM_BLOCKS ((N_NODES + BM - 1) / BM)              // 782
#define FILL_BLOCKS ((E_EDGES + 255) / 256)                // 3125
#define TOTAL_BLOCKS (GEMM_BLOCKS + FILL_BLOCKS)           // 3907

#define ZERO_BLOCKS 49                                     // 12500 int4 / 256
#define WCVT_BLOCKS 16                                     // 4096 float4 / 256
#define PREP_BLOCKS (ZERO_BLOCKS + WCVT_BLOCKS)

// ---------------------------------------------------------------------------
// Kernel A (prep): blocks [0,49) zero per-dst counters; blocks [49,65)
// convert W fp32 -> fp16 into g_Wh (row-major [n][k], same layout as W).
// ---------------------------------------------------------------------------
__global__ void prep_kernel(int* __restrict__ cnt,
                            const float* __restrict__ W,
                            __half* __restrict__ Wh) {
    if (blockIdx.x < ZERO_BLOCKS) {
        int i = blockIdx.x * blockDim.x + threadIdx.x;
        if (i < (N_NODES + 3) / 4)
            ((int4*)cnt)[i] = make_int4(0, 0, 0, 0);
    } else {
        int i = (blockIdx.x - ZERO_BLOCKS) * blockDim.x + threadIdx.x;  // 0..4095
        float4 v = ((const float4*)W)[i];
        union { uint2 u; __half2 h[2]; } pk;
        pk.h[0] = __floats2half2_rn(v.x, v.y);
        pk.h[1] = __floats2half2_rn(v.z, v.w);
        ((uint2*)Wh)[i] = pk.u;
    }
}

// ---------------------------------------------------------------------------
// GEMM body — R8 structure, but W arrives pre-converted fp16 (g_Wh):
// the 128x128 W tile is a straight 32KB uint4 copy (8 per thread), no
// conversion math.  64x128 tile, 48KB smem, 8 warps (2x4), 2x2 wmma frags.
// ---------------------------------------------------------------------------
__device__ __forceinline__ void gemm_body(
    const float* __restrict__ x,
    const __half* __restrict__ Wh,
    const float* __restrict__ b,
    __half* __restrict__ hidden,
    unsigned char* smem_raw,
    int gemm_id)
{
    __half* xs  = (__half*)smem_raw;            // [64][128]
    __half* wsm = xs + 64 * 128;                // [128][128]
    float*  out_s = (float*)smem_raw;           // [64][128] (epilogue reuse)

    const int tid = threadIdx.x;
    const int block_row = gemm_id * BM;

    // ---- x tile fp32->fp16: 64x128 = 2048 float4, 8/thread ----
#pragma unroll
    for (int i = 0; i < 8; i++) {
        const int idx = tid + i * 256;
        const int r = idx >> 5;
        const int c4 = idx & 31;
        const int grow = block_row + r;
        float4 v = make_float4(0.f, 0.f, 0.f, 0.f);
        if (grow < N_NODES)
            v = *(const float4*)&x[(size_t)grow * F + c4 * 4];
        *(__half2*)&xs[r * 128 + c4 * 4]     = __floats2half2_rn(v.x, v.y);
        *(__half2*)&xs[r * 128 + c4 * 4 + 2] = __floats2half2_rn(v.z, v.w);
    }
    // ---- W tile: 32KB fp16 straight copy, 2048 uint4, 8/thread ----
#pragma unroll
    for (int i = 0; i < 8; i++) {
        const int idx = tid + i * 256;          // 0..2047
        ((uint4*)wsm)[idx] = ((const uint4*)Wh)[idx];
    }
    __syncthreads();

    const int wid = tid >> 5;
    const int warp_m = wid & 1;
    const int warp_n = wid >> 1;

    wmma::fragment<wmma::accumulator, 16, 16, 16, float> acc[2][2];
#pragma unroll
    for (int im = 0; im < 2; im++)
#pragma unroll
        for (int jn = 0; jn < 2; jn++)
            wmma::fill_fragment(acc[im][jn], 0.f);

#pragma unroll
    for (int k0 = 0; k0 < F; k0 += 16) {
        wmma::fragment<wmma::matrix_a, 16, 16, 16, __half, wmma::row_major> a[2];
        wmma::fragment<wmma::matrix_b, 16, 16, 16, __half, wmma::col_major> bf[2];
#pragma unroll
        for (int im = 0; im < 2; im++)
            wmma::load_matrix_sync(a[im], &xs[(warp_m * 32 + im * 16) * 128 + k0], 128);
#pragma unroll
        for (int jn = 0; jn < 2; jn++)
            wmma::load_matrix_sync(bf[jn], &wsm[(warp_n * 32 + jn * 16) * 128 + k0], 128);
#pragma unroll
        for (int im = 0; im < 2; im++)
#pragma unroll
            for (int jn = 0; jn < 2; jn++)
                wmma::mma_sync(acc[im][jn], a[im], bf[jn], acc[im][jn]);
    }

    __syncthreads();
#pragma unroll
    for (int im = 0; im < 2; im++)
#pragma unroll
        for (int jn = 0; jn < 2; jn++)
            wmma::store_matrix_sync(
                &out_s[(warp_m * 32 + im * 16) * 128 + warp_n * 32 + jn * 16],
                acc[im][jn], 128, wmma::mem_row_major);
    __syncthreads();

#pragma unroll
    for (int i = 0; i < 8; i++) {
        const int idx = tid + i * 256;
        const int r = idx >> 5;
        const int c4 = idx & 31;
        const int grow = block_row + r;
        if (grow < N_NODES) {
            float4 v = *(const float4*)&out_s[r * 128 + c4 * 4];
            const float4 bias = *(const float4*)&b[c4 * 4];
            union { uint2 u; __half2 h[2]; } pk;
            pk.h[0] = __floats2half2_rn(v.x + bias.x, v.y + bias.y);
            pk.h[1] = __floats2half2_rn(v.z + bias.z, v.w + bias.w);
            *(uint2*)&hidden[(size_t)grow * F + c4 * 4] = pk.u;
        }
    }
}

// ---------------------------------------------------------------------------
// Fill body: bucket edges by dst.  edge_index int32 [2,E]: row0=dst, row1=src.
// ---------------------------------------------------------------------------
__device__ __forceinline__ void fill_body(
    const int* __restrict__ edge_index,
    const float* __restrict__ edge_weight,
    int* __restrict__ cnt,
    int2* __restrict__ slot,
    int fill_id)
{
    const int e = fill_id * 256 + threadIdx.x;
    if (e >= E_EDGES) return;
    const int dst = edge_index[e];
    const int src = edge_index[E_EDGES + e];
    const float w = edge_weight[e];
    const int pos = atomicAdd(&cnt[dst], 1);
    if (pos < CAP)
        slot[(size_t)dst * CAP + pos] = make_int2(src, __float_as_int(w));
}

// ---------------------------------------------------------------------------
// Fused kernel: range split, 48KB static smem.
// ---------------------------------------------------------------------------
__global__ __launch_bounds__(256) void gemm_fill_fused_kernel(
    const float* __restrict__ x,
    const __half* __restrict__ Wh,
    const float* __restrict__ b,
    const int* __restrict__ edge_index,
    const float* __restrict__ edge_weight,
    __half* __restrict__ hidden,
    int* __restrict__ cnt,
    int2* __restrict__ slot)
{
    __shared__ __align__(16) unsigned char smem_raw[48 * 1024];
    const int bid = blockIdx.x;
    if (bid < GEMM_BLOCKS) {
        gemm_body(x, Wh, b, hidden, smem_raw, bid);
    } else {
        fill_body(edge_index, edge_weight, cnt, slot, bid - GEMM_BLOCKS);
    }
}

// ---------------------------------------------------------------------------
// Gather SpMM — EXACT R11 structure (proven 70.1us total).  One warp per dst
// node; lane l owns feats 4l..4l+3 (8 fp16 B).  fp32 accumulation, unroll x4
// with PLAIN int2 slot loads.  No int4 cast, no cnt reset (proven poisons);
// x8 unroll measured neutral (R12) — keep x4.
// ---------------------------------------------------------------------------
__global__ __launch_bounds__(256) void spmm_gather_kernel(
    const int* __restrict__ cnt_arr,
    const int2* __restrict__ slot,
    const __half* __restrict__ hidden,
    float* __restrict__ out)
{
    const int node = blockIdx.x * (blockDim.x >> 5) + (threadIdx.x >> 5);
    const int lane = threadIdx.x & 31;
    if (node >= N_NODES) return;

    int cnt = cnt_arr[node];
    if (cnt > CAP) cnt = CAP;
    const int2* __restrict__ sl = &slot[(size_t)node * CAP];

    float4 acc = make_float4(0.f, 0.f, 0.f, 0.f);

    int j = 0;
    for (; j + 4 <= cnt; j += 4) {
        const int2 e0 = sl[j];
        const int2 e1 = sl[j + 1];
        const int2 e2 = sl[j + 2];
        const int2 e3 = sl[j + 3];
        const uint2 r0 = *(const uint2*)&hidden[(size_t)e0.x * F + lane * 4];
        const uint2 r1 = *(const uint2*)&hidden[(size_t)e1.x * F + lane * 4];
        const uint2 r2 = *(const uint2*)&hidden[(size_t)e2.x * F + lane * 4];
        const uint2 r3 = *(const uint2*)&hidden[(size_t)e3.x * F + lane * 4];
        const float w0 = __int_as_float(e0.y);
        const float w1 = __int_as_float(e1.y);
        const float w2 = __int_as_float(e2.y);
        const float w3 = __int_as_float(e3.y);
        float2 a01, a23;
        a01 = __half22float2(*(const __half2*)&r0.x);
        a23 = __half22float2(*(const __half2*)&r0.y);
        acc.x += w0 * a01.x; acc.y += w0 * a01.y; acc.z += w0 * a23.x; acc.w += w0 * a23.y;
        a01 = __half22float2(*(const __half2*)&r1.x);
        a23 = __half22float2(*(const __half2*)&r1.y);
        acc.x += w1 * a01.x; acc.y += w1 * a01.y; acc.z += w1 * a23.x; acc.w += w1 * a23.y;
        a01 = __half22float2(*(const __half2*)&r2.x);
        a23 = __half22float2(*(const __half2*)&r2.y);
        acc.x += w2 * a01.x; acc.y += w2 * a01.y; acc.z += w2 * a23.x; acc.w += w2 * a23.y;
        a01 = __half22float2(*(const __half2*)&r3.x);
        a23 = __half22float2(*(const __half2*)&r3.y);
        acc.x += w3 * a01.x; acc.y += w3 * a01.y; acc.z += w3 * a23.x; acc.w += w3 * a23.y;
    }
    for (; j + 2 <= cnt; j += 2) {
        const int2 e0 = sl[j];
        const int2 e1 = sl[j + 1];
        const uint2 r0 = *(const uint2*)&hidden[(size_t)e0.x * F + lane * 4];
        const uint2 r1 = *(const uint2*)&hidden[(size_t)e1.x * F + lane * 4];
        const float w0 = __int_as_float(e0.y);
        const float w1 = __int_as_float(e1.y);
        float2 a01, a23;
        a01 = __half22float2(*(const __half2*)&r0.x);
        a23 = __half22float2(*(const __half2*)&r0.y);
        acc.x += w0 * a01.x; acc.y += w0 * a01.y; acc.z += w0 * a23.x; acc.w += w0 * a23.y;
        a01 = __half22float2(*(const __half2*)&r1.x);
        a23 = __half22float2(*(const __half2*)&r1.y);
        acc.x += w1 * a01.x; acc.y += w1 * a01.y; acc.z += w1 * a23.x; acc.w += w1 * a23.y;
    }
    if (j < cnt) {
        const int2 e0 = sl[j];
        const uint2 r0 = *(const uint2*)&hidden[(size_t)e0.x * F + lane * 4];
        const float w0 = __int_as_float(e0.y);
        float2 a01 = __half22float2(*(const __half2*)&r0.x);
        float2 a23 = __half22float2(*(const __half2*)&r0.y);
        acc.x += w0 * a01.x; acc.y += w0 * a01.y; acc.z += w0 * a23.x; acc.w += w0 * a23.y;
    }
    *(float4*)&out[(size_t)node * F + lane * 4] = acc;
}

// ---------------------------------------------------------------------------
// Launch
// Inputs: x [N,128] f32, edge_index [2,E] i32, edge_weight [E] f32,
//         W [128,128] f32, b [128] f32.  Output: [N,128] f32.
// ---------------------------------------------------------------------------
extern "C" void kernel_launch(void* const* d_in, const int* in_sizes, int n_in,
                              void* d_out, int out_size) {
    const float* x  = (const float*)d_in[0];
    const int*   ei = (const int*)d_in[1];
    const float* ew = (const float*)d_in[2];
    const float* W  = (const float*)d_in[3];
    const float* b  = (const float*)d_in[4];
    float* out = (float*)d_out;

    __half* hidden; __half* Wh; int* cnt; int2* slot;
    cudaGetSymbolAddress((void**)&hidden, g_hidden);
    cudaGetSymbolAddress((void**)&Wh, g_Wh);
    cudaGetSymbolAddress((void**)&cnt, g_cnt);
    cudaGetSymbolAddress((void**)&slot, g_slot);

    // A) zero per-dst counters + convert W to fp16 (one prep kernel)
    prep_kernel<<<PREP_BLOCKS, 256>>>(cnt, W, Wh);

    // B) HMMA GEMM (fp16 W+hidden, 48KB smem) overlapped with edge bucketing
    gemm_fill_fused_kernel<<<TOTAL_BLOCKS, 256>>>(x, Wh, b, ei, ew, hidden, cnt, slot);

    // C) out[dst] = sum w * hidden[src]  (gather; writes all rows)
    {
        const int warps_per_block = 256 / 32;
        const int grid = (N_NODES + warps_per_block - 1) / warps_per_block;
        spmm_gather_kernel<<<grid, 256>>>(cnt, slot, hidden, out);
    }
}